// round 1
// baseline (speedup 1.0000x reference)
#include <cuda_runtime.h>
#include <math.h>

// Problem constants (from reference setup_inputs)
#define N_NODES 50000
#define KNN     8
#define NR      200000   // N * R

// ---------------- scratch (device globals; no runtime allocation) ----------------
__device__ float g_Wc_enc[64 * 128];                 // [k][ Wd_enc(64) | Wb_enc(64) ]
__device__ float g_Wc_ml [64 * 1024];                // [k][ Am(256)|Bm(256)|Alv(256)|Blv(256) ]
__device__ float g_AB1[(size_t)N_NODES * 128];       // x @ Wc_enc
__device__ float g_h  [(size_t)N_NODES * 64];        // encoder output
__device__ float g_AB2[(size_t)N_NODES * 1024];      // h @ Wc_ml  (~205 MB)
__device__ float g_z  [(size_t)NR * 64];             // reparametrized latent

// ---------------- weight preprocessing ----------------
// concat([xi, xj-xi]) @ W  ==  xi @ (W_top - W_bot) + xj @ W_bot
__global__ void prep_weights(const float* __restrict__ We,
                             const float* __restrict__ Wm,
                             const float* __restrict__ Wlv) {
    int idx = blockIdx.x * blockDim.x + threadIdx.x;
    if (idx < 64 * 128) {
        int k = idx >> 7, c = idx & 127;
        float v;
        if (c < 64) v = We[k * 64 + c] - We[(64 + k) * 64 + c];
        else        v = We[(64 + k) * 64 + (c - 64)];
        g_Wc_enc[idx] = v;
    }
    int idx2 = idx - 64 * 128;
    if (idx2 >= 0 && idx2 < 64 * 1024) {
        int k = idx2 >> 10, c = idx2 & 1023;
        int g = c >> 8, j = c & 255;
        float v;
        if      (g == 0) v = Wm [k * 256 + j] - Wm [(64 + k) * 256 + j];
        else if (g == 1) v = Wm [(64 + k) * 256 + j];
        else if (g == 2) v = Wlv[k * 256 + j] - Wlv[(64 + k) * 256 + j];
        else             v = Wlv[(64 + k) * 256 + j];
        g_Wc_ml[idx2] = v;
    }
}

// ---------------- SGEMM: C[M,Nout] = X[M,64] @ W[64,Nout] (+bias) ----------------
// 64x64 tile per 128-thread block; 4x8 microtile per thread.
__global__ void __launch_bounds__(128)
gemm64(const float* __restrict__ X, const float* __restrict__ W,
       float* __restrict__ Cout, int M, int Nout, const float* __restrict__ bias) {
    __shared__ float xs[64][68];   // pad 68: 16B-aligned rows, conflict-free column reads
    __shared__ float ws[64][64];

    int tid  = threadIdx.x;
    int row0 = blockIdx.x * 64;
    int col0 = blockIdx.y * 64;

    // stage X tile (zero-fill rows past M)
    #pragma unroll
    for (int i = 0; i < 8; i++) {
        int f  = tid + i * 128;      // 0..1023 float4s
        int r  = f >> 4;
        int c4 = (f & 15) * 4;
        float4 v;
        if (row0 + r < M) v = *(const float4*)(X + (size_t)(row0 + r) * 64 + c4);
        else              v = make_float4(0.f, 0.f, 0.f, 0.f);
        *(float4*)(&xs[r][c4]) = v;
    }
    // stage W tile
    #pragma unroll
    for (int i = 0; i < 8; i++) {
        int f  = tid + i * 128;
        int r  = f >> 4;
        int c4 = (f & 15) * 4;
        float4 v = *(const float4*)(W + (size_t)r * Nout + col0 + c4);
        *(float4*)(&ws[r][c4]) = v;
    }
    __syncthreads();

    int ty = tid >> 3;   // 0..15 -> rows ty + 16*i
    int tx = tid & 7;    // 0..7  -> cols tx + 8*j
    float acc[4][8];
    #pragma unroll
    for (int i = 0; i < 4; i++)
        #pragma unroll
        for (int j = 0; j < 8; j++) acc[i][j] = 0.f;

    #pragma unroll 8
    for (int k = 0; k < 64; k++) {
        float xv[4], wv[8];
        #pragma unroll
        for (int i = 0; i < 4; i++) xv[i] = xs[ty + 16 * i][k];
        #pragma unroll
        for (int j = 0; j < 8; j++) wv[j] = ws[k][tx + 8 * j];
        #pragma unroll
        for (int i = 0; i < 4; i++)
            #pragma unroll
            for (int j = 0; j < 8; j++)
                acc[i][j] = fmaf(xv[i], wv[j], acc[i][j]);
    }

    #pragma unroll
    for (int i = 0; i < 4; i++) {
        int r = row0 + ty + 16 * i;
        if (r < M) {
            #pragma unroll
            for (int j = 0; j < 8; j++) {
                int c = col0 + tx + 8 * j;
                float v = acc[i][j];
                if (bias) v += bias[c];
                Cout[(size_t)r * Nout + c] = v;
            }
        }
    }
}

// ---------------- encoder gather-max + bias + leaky_relu(0.2) ----------------
// 4 nodes per 256-thread block; thread j handles channel j of its node.
__global__ void __launch_bounds__(256)
gather_enc(const int* __restrict__ src, const float* __restrict__ b) {
    __shared__ int ss[32];
    int tid = threadIdx.x;
    if (tid < 32) ss[tid] = src[blockIdx.x * 32 + tid];
    __syncthreads();
    int local = tid >> 6;          // 0..3
    int j     = tid & 63;
    int node  = blockIdx.x * 4 + local;
    float a = g_AB1[(size_t)node * 128 + j];
    float m = -3.4e38f;
    #pragma unroll
    for (int k = 0; k < KNN; k++) {
        int s = ss[local * 8 + k];
        m = fmaxf(m, g_AB1[(size_t)s * 128 + 64 + j]);
    }
    float v = a + m + b[j];
    g_h[(size_t)node * 64 + j] = v > 0.f ? v : 0.2f * v;
}

// ---------------- mean/logvar gather-max + point_shuffle + reparametrize ----------------
// 1 node per 256-thread block; thread c handles channel c (0..255).
__global__ void __launch_bounds__(256)
gather_ml(const int* __restrict__ src, const float* __restrict__ noise,
          const float* __restrict__ bm, const float* __restrict__ blv) {
    __shared__ int ss[8];
    int tid  = threadIdx.x;
    int node = blockIdx.x;
    if (tid < 8) ss[tid] = src[node * 8 + tid];
    __syncthreads();
    size_t base = (size_t)node * 1024;
    float am  = g_AB2[base + tid];
    float alv = g_AB2[base + 512 + tid];
    float mm = -3.4e38f, mlv = -3.4e38f;
    #pragma unroll
    for (int k = 0; k < KNN; k++) {
        size_t sb = (size_t)ss[k] * 1024;
        mm  = fmaxf(mm,  g_AB2[sb + 256 + tid]);
        mlv = fmaxf(mlv, g_AB2[sb + 768 + tid]);
    }
    float zm  = am  + mm  + bm[tid];
    float zlv = alv + mlv + blv[tid];
    // point_shuffle: c = c2*R + r  ->  out[node*R + r][c2]
    int r  = tid & 3;
    int c2 = tid >> 2;
    size_t o = (size_t)(node * 4 + r) * 64 + c2;
    g_z[o] = zm + noise[o] * expf(0.5f * zlv);
}

// ---------------- launch ----------------
extern "C" void kernel_launch(void* const* d_in, const int* in_sizes, int n_in,
                              void* d_out, int out_size) {
    const float* x     = (const float*)d_in[0];
    const int*   src   = (const int*)  d_in[1];
    // d_in[2] = edge_dst: known to be repeat(arange(N), K); segments are implicit
    const float* noise = (const float*)d_in[3];
    const float* We    = (const float*)d_in[4];
    const float* be    = (const float*)d_in[5];
    const float* Wm    = (const float*)d_in[6];
    const float* bm    = (const float*)d_in[7];
    const float* Wlv   = (const float*)d_in[8];
    const float* blv   = (const float*)d_in[9];
    const float* Wd    = (const float*)d_in[10];
    const float* bd    = (const float*)d_in[11];
    float* out = (float*)d_out;

    float *pWcE, *pWcML, *pAB1, *pH, *pAB2, *pZ;
    cudaGetSymbolAddress((void**)&pWcE,  g_Wc_enc);
    cudaGetSymbolAddress((void**)&pWcML, g_Wc_ml);
    cudaGetSymbolAddress((void**)&pAB1,  g_AB1);
    cudaGetSymbolAddress((void**)&pH,    g_h);
    cudaGetSymbolAddress((void**)&pAB2,  g_AB2);
    cudaGetSymbolAddress((void**)&pZ,    g_z);

    // 1. combined weights
    prep_weights<<<288, 256>>>(We, Wm, Wlv);
    // 2. AB1 = x @ [Wd_enc | Wb_enc]   (50000 x 128)
    gemm64<<<dim3(782, 2), 128>>>(x, pWcE, pAB1, N_NODES, 128, nullptr);
    // 3. h = leaky(A + max_k B[src] + b)
    gather_enc<<<12500, 256>>>(src, be);
    // 4. AB2 = h @ [Am|Bm|Alv|Blv]     (50000 x 1024)
    gemm64<<<dim3(782, 16), 128>>>(pH, pWcML, pAB2, N_NODES, 1024, nullptr);
    // 5. gather-max x2 + shuffle + reparametrize -> z (200000 x 64)
    gather_ml<<<N_NODES, 256>>>(src, noise, bm, blv);
    // 6. out = z @ W_dec + b_dec
    gemm64<<<dim3(3125, 1), 128>>>(pZ, Wd, out, NR, 64, bd);
}

// round 2
// speedup vs baseline: 1.0321x; 1.0321x over previous
#include <cuda_runtime.h>
#include <math.h>

#define N_NODES 50000
#define KNN     8
#define NR      200000   // N * R

// ---------------- scratch (device globals) ----------------
__device__ float g_Wc_enc[64 * 128];                 // [k][ Wd_enc | Wb_enc ]
__device__ float g_W_A[64 * 512];                    // [k][ Am(256) | Alv(256) ]
__device__ float g_W_B[64 * 512];                    // [k][ Bm(256) | Blv(256) ]
__device__ float g_AB1[(size_t)N_NODES * 128];
__device__ float g_h  [(size_t)N_NODES * 64];
__device__ float g_A2 [(size_t)N_NODES * 512];       // own-part (streamed once)
__device__ float g_B2 [(size_t)N_NODES * 512];       // neighbor-part (102MB, L2-resident)
__device__ float g_z  [(size_t)NR * 64];

// ---------------- weight prep ----------------
// concat([xi, xj-xi]) @ W == xi @ (W_top - W_bot) + xj @ W_bot
__global__ void prep_weights(const float* __restrict__ We,
                             const float* __restrict__ Wm,
                             const float* __restrict__ Wlv) {
    int idx = blockIdx.x * blockDim.x + threadIdx.x;
    if (idx < 64 * 128) {
        int k = idx >> 7, c = idx & 127;
        g_Wc_enc[idx] = (c < 64) ? We[k * 64 + c] - We[(64 + k) * 64 + c]
                                 : We[(64 + k) * 64 + (c - 64)];
    }
    int i2 = idx - 64 * 128;
    if (i2 >= 0 && i2 < 64 * 512) {
        int k = i2 >> 9, c = i2 & 511;
        float a, b;
        if (c < 256) {
            a = Wm[k * 256 + c] - Wm[(64 + k) * 256 + c];
            b = Wm[(64 + k) * 256 + c];
        } else {
            int j = c - 256;
            a = Wlv[k * 256 + j] - Wlv[(64 + k) * 256 + j];
            b = Wlv[(64 + k) * 256 + j];
        }
        g_W_A[i2] = a;
        g_W_B[i2] = b;
    }
}

// ---------------- SGEMM: C[M,Nout] = X[M,64] @ W[64,Nout] (+bias) ----------------
// BM=128 x BN tile, 256 threads, 8x(BN/16) microtile, all-vector LDS.
template<int BN>
__global__ void __launch_bounds__(256)
gemm_t(const float* __restrict__ X, const float* __restrict__ W,
       float* __restrict__ C, int M, int Nout, const float* __restrict__ bias)
{
    constexpr int KC  = 32;
    constexpr int XSS = 128 + 4;          // float stride: 528B = 33*16, float4-aligned
    constexpr int NG  = BN / 64;          // 1 or 2 column groups of 64
    __shared__ float xsT[KC * XSS];       // 16.9 KB  (X transposed: [k][r])
    __shared__ float ws [KC * BN];        // 16 KB / 8 KB

    const int tid  = threadIdx.x;
    const int row0 = blockIdx.x * 128;
    const int col0 = blockIdx.y * BN;
    const int ty   = tid >> 4;            // rows ty*8 .. ty*8+7
    const int tx   = tid & 15;            // cols g*64 + tx*4 .. +3

    float acc[8][NG * 4];
    #pragma unroll
    for (int r = 0; r < 8; r++)
        #pragma unroll
        for (int c = 0; c < NG * 4; c++) acc[r][c] = 0.f;

    for (int kc = 0; kc < 64; kc += KC) {
        // stage X^T: r-fast mapping -> STS bank-conflict-free
        #pragma unroll
        for (int i = 0; i < 4; i++) {
            int f  = tid + i * 256;       // 0..1023 float4s
            int r  = f & 127;
            int k4 = (f >> 7) * 4;        // 0,4,...,28
            float4 v = make_float4(0.f, 0.f, 0.f, 0.f);
            if (row0 + r < M)
                v = *(const float4*)(X + (size_t)(row0 + r) * 64 + kc + k4);
            xsT[(k4 + 0) * XSS + r] = v.x;
            xsT[(k4 + 1) * XSS + r] = v.y;
            xsT[(k4 + 2) * XSS + r] = v.z;
            xsT[(k4 + 3) * XSS + r] = v.w;
        }
        // stage W tile (coalesced)
        #pragma unroll
        for (int i = 0; i < BN / 32; i++) {
            int f  = tid + i * 256;
            int k  = f / (BN / 4);
            int c4 = (f % (BN / 4)) * 4;
            *(float4*)(ws + k * BN + c4) =
                *(const float4*)(W + (size_t)(kc + k) * Nout + col0 + c4);
        }
        __syncthreads();

        #pragma unroll
        for (int k = 0; k < KC; k++) {
            float4 xa = *(const float4*)(xsT + k * XSS + ty * 8);
            float4 xb = *(const float4*)(xsT + k * XSS + ty * 8 + 4);
            float xr[8] = {xa.x, xa.y, xa.z, xa.w, xb.x, xb.y, xb.z, xb.w};
            #pragma unroll
            for (int g = 0; g < NG; g++) {
                float4 wv = *(const float4*)(ws + k * BN + g * 64 + tx * 4);
                float wr[4] = {wv.x, wv.y, wv.z, wv.w};
                #pragma unroll
                for (int r = 0; r < 8; r++)
                    #pragma unroll
                    for (int c = 0; c < 4; c++)
                        acc[r][g * 4 + c] = fmaf(xr[r], wr[c], acc[r][g * 4 + c]);
            }
        }
        __syncthreads();
    }

    #pragma unroll
    for (int r = 0; r < 8; r++) {
        int row = row0 + ty * 8 + r;
        if (row < M) {
            #pragma unroll
            for (int g = 0; g < NG; g++) {
                int c = col0 + g * 64 + tx * 4;
                float4 v;
                v.x = acc[r][g * 4 + 0];
                v.y = acc[r][g * 4 + 1];
                v.z = acc[r][g * 4 + 2];
                v.w = acc[r][g * 4 + 3];
                if (bias) {
                    float4 bv = *(const float4*)(bias + c);
                    v.x += bv.x; v.y += bv.y; v.z += bv.z; v.w += bv.w;
                }
                *(float4*)(C + (size_t)row * Nout + c) = v;
            }
        }
    }
}

// ---------------- encoder gather-max + bias + leaky_relu(0.2) ----------------
__global__ void __launch_bounds__(256)
gather_enc(const int* __restrict__ src, const float* __restrict__ b) {
    __shared__ int ss[32];
    int tid = threadIdx.x;
    if (tid < 32) ss[tid] = src[blockIdx.x * 32 + tid];
    __syncthreads();
    int local = tid >> 6;
    int j     = tid & 63;
    int node  = blockIdx.x * 4 + local;
    float a = __ldcs(g_AB1 + (size_t)node * 128 + j);
    float m = -3.4e38f;
    #pragma unroll
    for (int k = 0; k < KNN; k++) {
        int s = ss[local * 8 + k];
        m = fmaxf(m, g_AB1[(size_t)s * 128 + 64 + j]);
    }
    float v = a + m + b[j];
    g_h[(size_t)node * 64 + j] = v > 0.f ? v : 0.2f * v;
}

// ---------------- mean/logvar gather-max + shuffle + reparametrize ----------------
// 1 node per 256-thread block; thread c handles mean chan c and logvar chan c.
__global__ void __launch_bounds__(256)
gather_ml(const int* __restrict__ src, const float* __restrict__ noise,
          const float* __restrict__ bm, const float* __restrict__ blv) {
    __shared__ int ss[KNN];
    int tid  = threadIdx.x;
    int node = blockIdx.x;
    if (tid < KNN) ss[tid] = src[node * KNN + tid];
    __syncthreads();
    size_t abase = (size_t)node * 512;
    float am  = __ldcs(g_A2 + abase + tid);          // streamed: protect B2 in L2
    float alv = __ldcs(g_A2 + abase + 256 + tid);
    float mm = -3.4e38f, mlv = -3.4e38f;
    #pragma unroll
    for (int k = 0; k < KNN; k++) {
        size_t sb = (size_t)ss[k] * 512;
        mm  = fmaxf(mm,  g_B2[sb + tid]);
        mlv = fmaxf(mlv, g_B2[sb + 256 + tid]);
    }
    float zm  = am  + mm  + bm[tid];
    float zlv = alv + mlv + blv[tid];
    int r  = tid & 3;
    int c2 = tid >> 2;
    size_t o = (size_t)(node * 4 + r) * 64 + c2;
    float nz = __ldcs(noise + o);
    g_z[o] = fmaf(nz, expf(0.5f * zlv), zm);
}

// ---------------- launch ----------------
extern "C" void kernel_launch(void* const* d_in, const int* in_sizes, int n_in,
                              void* d_out, int out_size) {
    const float* x     = (const float*)d_in[0];
    const int*   src   = (const int*)  d_in[1];
    const float* noise = (const float*)d_in[3];
    const float* We    = (const float*)d_in[4];
    const float* be    = (const float*)d_in[5];
    const float* Wm    = (const float*)d_in[6];
    const float* bm    = (const float*)d_in[7];
    const float* Wlv   = (const float*)d_in[8];
    const float* blv   = (const float*)d_in[9];
    const float* Wd    = (const float*)d_in[10];
    const float* bd    = (const float*)d_in[11];
    float* out = (float*)d_out;

    float *pWcE, *pWA, *pWB, *pAB1, *pH, *pA2, *pB2, *pZ;
    cudaGetSymbolAddress((void**)&pWcE, g_Wc_enc);
    cudaGetSymbolAddress((void**)&pWA,  g_W_A);
    cudaGetSymbolAddress((void**)&pWB,  g_W_B);
    cudaGetSymbolAddress((void**)&pAB1, g_AB1);
    cudaGetSymbolAddress((void**)&pH,   g_h);
    cudaGetSymbolAddress((void**)&pA2,  g_A2);
    cudaGetSymbolAddress((void**)&pB2,  g_B2);
    cudaGetSymbolAddress((void**)&pZ,   g_z);

    // 1. combined weights
    prep_weights<<<160, 256>>>(We, Wm, Wlv);
    // 2. AB1 = x @ [Wd_enc | Wb_enc]   (50000 x 128)
    gemm_t<128><<<dim3(391, 1), 256>>>(x, pWcE, pAB1, N_NODES, 128, nullptr);
    // 3. h = leaky(A + max_k B[src] + b)
    gather_enc<<<12500, 256>>>(src, be);
    // 4a. A2 = h @ [Am|Alv]   (50000 x 512, own-part)
    gemm_t<128><<<dim3(391, 4), 256>>>(pH, pWA, pA2, N_NODES, 512, nullptr);
    // 4b. B2 = h @ [Bm|Blv]   (50000 x 512, neighbor-part, L2-resident for gather)
    gemm_t<128><<<dim3(391, 4), 256>>>(pH, pWB, pB2, N_NODES, 512, nullptr);
    // 5. gather-max x2 + shuffle + reparametrize -> z (200000 x 64)
    gather_ml<<<N_NODES, 256>>>(src, noise, bm, blv);
    // 6. out = z @ W_dec + b_dec
    gemm_t<64><<<dim3(1563, 1), 256>>>(pZ, Wd, out, NR, 64, bd);
}

// round 4
// speedup vs baseline: 1.4963x; 1.4498x over previous
#include <cuda_runtime.h>
#include <math.h>

#define N_NODES 50000
#define KNN     8
#define NR      200000   // N * R

// ---------------- scratch (device globals) ----------------
__device__ float g_Wc_enc[64 * 128];                 // [k][ Wd_enc | Wb_enc ]
__device__ float g_W_A[64 * 512];                    // [k][ Am(256) | Alv(256) ]
__device__ float g_W_B[64 * 512];                    // [k][ Bm(256) | Blv(256) ]
__device__ float g_AB1[(size_t)N_NODES * 128];
__device__ float g_h  [(size_t)N_NODES * 64];
__device__ float g_A2 [(size_t)N_NODES * 512];       // own-part (streamed once)
__device__ float g_B2 [(size_t)N_NODES * 512];       // neighbor-part (102MB, L2-friendly)
__device__ float g_z  [(size_t)NR * 64];

// ---------------- weight prep ----------------
// concat([xi, xj-xi]) @ W == xi @ (W_top - W_bot) + xj @ W_bot
__global__ void prep_weights(const float* __restrict__ We,
                             const float* __restrict__ Wm,
                             const float* __restrict__ Wlv) {
    int idx = blockIdx.x * blockDim.x + threadIdx.x;
    if (idx < 64 * 128) {
        int k = idx >> 7, c = idx & 127;
        g_Wc_enc[idx] = (c < 64) ? We[k * 64 + c] - We[(64 + k) * 64 + c]
                                 : We[(64 + k) * 64 + (c - 64)];
    }
    int i2 = idx - 64 * 128;
    if (i2 >= 0 && i2 < 64 * 512) {
        int k = i2 >> 9, c = i2 & 511;
        float a, b;
        if (c < 256) {
            a = Wm[k * 256 + c] - Wm[(64 + k) * 256 + c];
            b = Wm[(64 + k) * 256 + c];
        } else {
            int j = c - 256;
            a = Wlv[k * 256 + j] - Wlv[(64 + k) * 256 + j];
            b = Wlv[(64 + k) * 256 + j];
        }
        g_W_A[i2] = a;
        g_W_B[i2] = b;
    }
}

// ---------------- tf32 tensor-core GEMM ----------------
// C[M,Nout] = X[M,64] @ W[64,Nout] (+bias), Nout % 64 == 0.
// Block: 128x64 tile, 256 threads (8 warps, 4x2 warp grid, 32x32 warp tile).
// Whole K=64 staged in dynamic smem once. mma.sync.m16n8k8.tf32.
#define XS 68   // xs row stride (floats): conflict-free A frags + aligned staging
#define WS 68   // ws row stride
#define GEMM_SMEM ((128 * XS + 64 * WS) * 4)

__device__ __forceinline__ float to_tf32(float x) {
    unsigned r;
    asm("cvt.rna.tf32.f32 %0, %1;" : "=r"(r) : "f"(x));
    return __uint_as_float(r);
}

__global__ void __launch_bounds__(256)
gemm_tc(const float* __restrict__ X, const float* __restrict__ W,
        float* __restrict__ C, int M, int Nout, const float* __restrict__ bias)
{
    extern __shared__ float sm[];
    float* xs = sm;                 // [128][XS]  X tile (tf32-rounded)
    float* ws = sm + 128 * XS;      // [64][WS]   W tile (tf32-rounded), [k][n]

    const int tid  = threadIdx.x;
    const int row0 = blockIdx.x * 128;
    const int col0 = blockIdx.y * 64;

    // stage X: 128 rows x 64 cols = 2048 float4
    #pragma unroll
    for (int i = 0; i < 8; i++) {
        int f  = tid + i * 256;
        int r  = f >> 4;
        int c4 = (f & 15) * 4;
        float4 v = make_float4(0.f, 0.f, 0.f, 0.f);
        if (row0 + r < M) v = *(const float4*)(X + (size_t)(row0 + r) * 64 + c4);
        float* p = xs + r * XS + c4;
        p[0] = to_tf32(v.x); p[1] = to_tf32(v.y);
        p[2] = to_tf32(v.z); p[3] = to_tf32(v.w);
    }
    // stage W: 64 rows x 64 cols = 1024 float4
    #pragma unroll
    for (int i = 0; i < 4; i++) {
        int f  = tid + i * 256;
        int r  = f >> 4;
        int c4 = (f & 15) * 4;
        float4 v = *(const float4*)(W + (size_t)r * Nout + col0 + c4);
        float* p = ws + r * WS + c4;
        p[0] = to_tf32(v.x); p[1] = to_tf32(v.y);
        p[2] = to_tf32(v.z); p[3] = to_tf32(v.w);
    }
    __syncthreads();

    const int warp = tid >> 5;
    const int lane = tid & 31;
    const int wr   = warp >> 1;          // 0..3 -> rows wr*32
    const int wc   = warp & 1;           // 0..1 -> cols wc*32
    const int qr   = lane >> 2;          // 0..7
    const int qc   = lane & 3;           // 0..3

    float acc[2][4][4];
    #pragma unroll
    for (int mi = 0; mi < 2; mi++)
        #pragma unroll
        for (int ni = 0; ni < 4; ni++)
            #pragma unroll
            for (int t = 0; t < 4; t++) acc[mi][ni][t] = 0.f;

    #pragma unroll
    for (int k0 = 0; k0 < 64; k0 += 8) {
        unsigned a[2][4], b[4][2];
        #pragma unroll
        for (int mi = 0; mi < 2; mi++) {
            const float* p = xs + (wr * 32 + mi * 16 + qr) * XS + k0 + qc;
            a[mi][0] = __float_as_uint(p[0]);
            a[mi][1] = __float_as_uint(p[8 * XS]);
            a[mi][2] = __float_as_uint(p[4]);
            a[mi][3] = __float_as_uint(p[8 * XS + 4]);
        }
        #pragma unroll
        for (int ni = 0; ni < 4; ni++) {
            const float* p = ws + (k0 + qc) * WS + wc * 32 + ni * 8 + qr;
            b[ni][0] = __float_as_uint(p[0]);
            b[ni][1] = __float_as_uint(p[4 * WS]);
        }
        #pragma unroll
        for (int mi = 0; mi < 2; mi++)
            #pragma unroll
            for (int ni = 0; ni < 4; ni++)
                asm volatile(
                    "mma.sync.aligned.m16n8k8.row.col.f32.tf32.tf32.f32 "
                    "{%0,%1,%2,%3}, {%4,%5,%6,%7}, {%8,%9}, {%0,%1,%2,%3};"
                    : "+f"(acc[mi][ni][0]), "+f"(acc[mi][ni][1]),
                      "+f"(acc[mi][ni][2]), "+f"(acc[mi][ni][3])
                    : "r"(a[mi][0]), "r"(a[mi][1]), "r"(a[mi][2]), "r"(a[mi][3]),
                      "r"(b[ni][0]), "r"(b[ni][1]));
    }

    // epilogue: c0,c1 -> (qr, qc*2+{0,1}); c2,c3 -> (qr+8, qc*2+{0,1})
    #pragma unroll
    for (int mi = 0; mi < 2; mi++) {
        #pragma unroll
        for (int half = 0; half < 2; half++) {
            int row = row0 + wr * 32 + mi * 16 + qr + half * 8;
            if (row < M) {
                #pragma unroll
                for (int ni = 0; ni < 4; ni++) {
                    int col = col0 + wc * 32 + ni * 8 + qc * 2;
                    float2 v;
                    v.x = acc[mi][ni][half * 2 + 0];
                    v.y = acc[mi][ni][half * 2 + 1];
                    if (bias) {
                        float2 bv = *(const float2*)(bias + col);
                        v.x += bv.x; v.y += bv.y;
                    }
                    *(float2*)(C + (size_t)row * Nout + col) = v;
                }
            }
        }
    }
}

// ---------------- encoder gather-max + bias + leaky_relu(0.2) ----------------
__global__ void __launch_bounds__(256)
gather_enc(const int* __restrict__ src, const float* __restrict__ b) {
    __shared__ int ss[32];
    int tid = threadIdx.x;
    if (tid < 32) ss[tid] = src[blockIdx.x * 32 + tid];
    __syncthreads();
    int local = tid >> 6;
    int j     = tid & 63;
    int node  = blockIdx.x * 4 + local;
    float a = __ldcs(g_AB1 + (size_t)node * 128 + j);
    float m = -3.4e38f;
    #pragma unroll
    for (int k = 0; k < KNN; k++) {
        int s = ss[local * 8 + k];
        m = fmaxf(m, g_AB1[(size_t)s * 128 + 64 + j]);
    }
    float v = a + m + b[j];
    g_h[(size_t)node * 64 + j] = v > 0.f ? v : 0.2f * v;
}

// ---------------- mean/logvar gather-max + shuffle + reparametrize ----------------
__global__ void __launch_bounds__(256)
gather_ml(const int* __restrict__ src, const float* __restrict__ noise,
          const float* __restrict__ bm, const float* __restrict__ blv) {
    __shared__ int ss[KNN];
    int tid  = threadIdx.x;
    int node = blockIdx.x;
    if (tid < KNN) ss[tid] = src[node * KNN + tid];
    __syncthreads();
    size_t abase = (size_t)node * 512;
    float am  = __ldcs(g_A2 + abase + tid);          // streamed: protect B2 in L2
    float alv = __ldcs(g_A2 + abase + 256 + tid);
    float mm = -3.4e38f, mlv = -3.4e38f;
    #pragma unroll
    for (int k = 0; k < KNN; k++) {
        size_t sb = (size_t)ss[k] * 512;
        mm  = fmaxf(mm,  g_B2[sb + tid]);
        mlv = fmaxf(mlv, g_B2[sb + 256 + tid]);
    }
    float zm  = am  + mm  + bm[tid];
    float zlv = alv + mlv + blv[tid];
    int r  = tid & 3;
    int c2 = tid >> 2;
    size_t o = (size_t)(node * 4 + r) * 64 + c2;
    float nz = __ldcs(noise + o);
    g_z[o] = fmaf(nz, expf(0.5f * zlv), zm);
}

// ---------------- launch ----------------
extern "C" void kernel_launch(void* const* d_in, const int* in_sizes, int n_in,
                              void* d_out, int out_size) {
    const float* x     = (const float*)d_in[0];
    const int*   src   = (const int*)  d_in[1];
    const float* noise = (const float*)d_in[3];
    const float* We    = (const float*)d_in[4];
    const float* be    = (const float*)d_in[5];
    const float* Wm    = (const float*)d_in[6];
    const float* bm    = (const float*)d_in[7];
    const float* Wlv   = (const float*)d_in[8];
    const float* blv   = (const float*)d_in[9];
    const float* Wd    = (const float*)d_in[10];
    const float* bd    = (const float*)d_in[11];
    float* out = (float*)d_out;

    float *pWcE, *pWA, *pWB, *pAB1, *pH, *pA2, *pB2, *pZ;
    cudaGetSymbolAddress((void**)&pWcE, g_Wc_enc);
    cudaGetSymbolAddress((void**)&pWA,  g_W_A);
    cudaGetSymbolAddress((void**)&pWB,  g_W_B);
    cudaGetSymbolAddress((void**)&pAB1, g_AB1);
    cudaGetSymbolAddress((void**)&pH,   g_h);
    cudaGetSymbolAddress((void**)&pA2,  g_A2);
    cudaGetSymbolAddress((void**)&pB2,  g_B2);
    cudaGetSymbolAddress((void**)&pZ,   g_z);

    cudaFuncSetAttribute(gemm_tc, cudaFuncAttributeMaxDynamicSharedMemorySize,
                         GEMM_SMEM);

    // 1. combined weights
    prep_weights<<<160, 256>>>(We, Wm, Wlv);
    // 2. AB1 = x @ [Wd_enc | Wb_enc]   (50000 x 128)
    gemm_tc<<<dim3(391, 2), 256, GEMM_SMEM>>>(x, pWcE, pAB1, N_NODES, 128, nullptr);
    // 3. h = leaky(A + max_k B[src] + b)
    gather_enc<<<12500, 256>>>(src, be);
    // 4a. A2 = h @ [Am|Alv]   (50000 x 512, own-part)
    gemm_tc<<<dim3(391, 8), 256, GEMM_SMEM>>>(pH, pWA, pA2, N_NODES, 512, nullptr);
    // 4b. B2 = h @ [Bm|Blv]   (50000 x 512, neighbor-part)
    gemm_tc<<<dim3(391, 8), 256, GEMM_SMEM>>>(pH, pWB, pB2, N_NODES, 512, nullptr);
    // 5. gather-max x2 + shuffle + reparametrize -> z (200000 x 64)
    gather_ml<<<N_NODES, 256>>>(src, noise, bm, blv);
    // 6. out = z @ W_dec + b_dec
    gemm_tc<<<dim3(1563, 1), 256, GEMM_SMEM>>>(pZ, Wd, out, NR, 64, bd);
}